// round 14
// baseline (speedup 1.0000x reference)
#include <cuda_runtime.h>
#include <cuda_fp16.h>
#include <math.h>
#include <stdint.h>

// ---------------------------------------------------------------------------
// KoopmanPhiICNN encode, R14: single-pass fp16 mma.sync, BKT=64, and
// K-concatenated forward: activations stored [h | z] (width 1088), weights
// [softplus(Wz) | Wx_z] pre-concatenated -> hidden fwd = ONE 17-stage GEMM.
// Scaling: activations x2^-5, weights x2^5, grad scales s3=1,s2=1,s1=2^-4,
// s0=2^-13 (exact powers of 2). 3-stage cp.async pipeline, 256 thr.
// ---------------------------------------------------------------------------

#define Bsz 4096
#define Hd  832
#define Zd  256
#define HW  1088          // Hd + Zd (concatenated activation width)
#define BH  (Bsz*Hd)
#define BHW (4096ull*1088ull)
#define HH  (Hd*Hd)
#define BZ  (Bsz*Zd)
#define NSTEPS 64

#define BM 128
#define BN 64
#define BKT 64
#define BK 16
#define NTHR 256
#define NSTAGE 3

#define SCL   32.0f
#define ISCL  0.03125f

// ---- fp32 scratch ----
#define O_SWZO 0ull
#define O_C    (O_SWZO + 1024ull)
#define O_G    (O_C + 4ull*BH)
#define O_M    (O_G + (unsigned long long)BZ)
#define O_V    (O_M + (unsigned long long)BZ)
#define TOTALF (O_V + (unsigned long long)BZ)
__device__ __align__(16) float g_buf[TOTALF];

// ---- fp16 scratch ----
#define SZ_WINZ  (832ull*256ull)
#define SZ_BC    (3ull*832ull*1088ull)
#define SZ_SWZ   (3ull*(unsigned long long)HH)
#define SZ_WXZ   (3ull*832ull*256ull)
#define OB_WINZ   0ull
#define OB_BC     (OB_WINZ + SZ_WINZ)
#define OB_SWZT   (OB_BC + SZ_BC)
#define OB_WXZT   (OB_SWZT + SZ_SWZ)
#define OB_WINZT  (OB_WXZT + SZ_WXZ)
#define OB_H      (OB_WINZT + SZ_WINZ)
#define OB_DA     (OB_H + 3ull*BHW)
#define OB_DB     (OB_DA + (unsigned long long)BH)
#define OB_Z      (OB_DB + (unsigned long long)BH)
#define TOTALH    (OB_Z + (unsigned long long)BZ)
__device__ __align__(16) __half g_hf[TOTALH];

__device__ __forceinline__ float sp_(float x) {
    return fmaxf(x, 0.f) + log1pf(expf(-fabsf(x)));
}
__device__ __forceinline__ float sig_(float x) { return 1.f / (1.f + expf(-x)); }
__device__ __forceinline__ float sig_from_h(float h) { return -expm1f(-h); }

// ---------------------------------------------------------------------------
// TN tensor-core GEMM core: C[128,64] += A[128,K]*B[64,K]^T, single fp16,
// K-stage = 64 (rows of 64 halves, stride SA=72 -> conflict-free ldsm).
// ---------------------------------------------------------------------------
#define SA 72
#define OFF_A  0
#define OFF_B  (128*SA)
#define STAGE_H ((128+64)*SA)               // 13824 halves = 27648 B
#define SMEM_BYTES (NSTAGE*2*STAGE_H)       // 82944 B

__device__ __forceinline__ void ldsm4(uint32_t* r, uint32_t addr) {
    asm volatile("ldmatrix.sync.aligned.m8n8.x4.shared.b16 {%0,%1,%2,%3}, [%4];\n"
        : "=r"(r[0]), "=r"(r[1]), "=r"(r[2]), "=r"(r[3]) : "r"(addr));
}
__device__ __forceinline__ void mmah(float* c, const uint32_t* a, uint32_t b0, uint32_t b1) {
    asm volatile("mma.sync.aligned.m16n8k16.row.col.f32.f16.f16.f32 "
        "{%0,%1,%2,%3},{%4,%5,%6,%7},{%8,%9},{%0,%1,%2,%3};\n"
        : "+f"(c[0]), "+f"(c[1]), "+f"(c[2]), "+f"(c[3])
        : "r"(a[0]), "r"(a[1]), "r"(a[2]), "r"(a[3]), "r"(b0), "r"(b1));
}
__device__ __forceinline__ void cp16(uint32_t dst, const void* src) {
    asm volatile("cp.async.cg.shared.global [%0], [%1], 16;\n" :: "r"(dst), "l"(src));
}
__device__ __forceinline__ void cpcommit() { asm volatile("cp.async.commit_group;\n"); }
template<int N> __device__ __forceinline__ void cpwait() {
    asm volatile("cp.async.wait_group %0;\n" :: "n"(N));
}

__device__ __forceinline__ void ld_stage(uint32_t smst,
    const __half* __restrict__ A, int lda,
    const __half* __restrict__ B, int ldb,
    int m0, int n0, int k0, int tid)
{
#pragma unroll
    for (int h = 0; h < 4; h++) {
        int ch = tid + h * 256;
        int row = ch >> 3, kc = ch & 7;
        size_t go = (size_t)(m0 + row) * lda + k0 + kc * 8;
        uint32_t so = smst + 2 * (OFF_A + row * SA + kc * 8);
        cp16(so, A + go);
    }
#pragma unroll
    for (int h = 0; h < 2; h++) {
        int ch = tid + h * 256;
        int row = ch >> 3, kc = ch & 7;
        size_t go = (size_t)(n0 + row) * ldb + k0 + kc * 8;
        uint32_t so = smst + 2 * (OFF_B + row * SA + kc * 8);
        cp16(so, B + go);
    }
}

__device__ __forceinline__ void compute_stage(float acc[2][4][4], uint32_t smst,
                                              int lane, int wm, int wn)
{
#pragma unroll
    for (int kk = 0; kk < 4; kk++) {
        const int k16 = kk * 16;
        uint32_t a0[4], a1[4];
        {
            int arow = lane & 15;
            int akoff = k16 + ((lane >> 4) << 3);
            uint32_t ad = smst + 2 * ((wm + arow) * SA + akoff);
            ldsm4(a0, ad);
            ldsm4(a1, ad + 2 * 16 * SA);
        }
        uint32_t b0[4], b1[4];
        {
            int brow = ((lane >> 4) << 3) + (lane & 7);
            int bkoff = k16 + (((lane >> 3) & 1) << 3);
            uint32_t bd = smst + 2 * (OFF_B + (wn + brow) * SA + bkoff);
            ldsm4(b0, bd);
            ldsm4(b1, bd + 2 * 16 * SA);
        }
#pragma unroll
        for (int mi = 0; mi < 2; mi++) {
            const uint32_t* Af = mi ? a1 : a0;
#pragma unroll
            for (int ni = 0; ni < 4; ni++) {
                const uint32_t* Bf = (ni < 2) ? b0 : b1;
                int h2 = (ni & 1) * 2;
                mmah(acc[mi][ni], Af, Bf[h2], Bf[h2 + 1]);
            }
        }
    }
}

__device__ __forceinline__ void gemm_tn(float acc[2][4][4], uint32_t smbase,
    const __half* A, int lda,
    const __half* B, int ldb,
    int kt, int m0, int n0, int tid, int lane, int wm, int wn)
{
    __syncthreads();
    ld_stage(smbase, A, lda, B, ldb, m0, n0, 0, tid);
    cpcommit();
    if (kt > 1) ld_stage(smbase + 2 * STAGE_H, A, lda, B, ldb, m0, n0, BKT, tid);
    cpcommit();

    for (int t = 0; t < kt; t++) {
        cpwait<1>();
        __syncthreads();
        compute_stage(acc, smbase + (t % 3) * 2 * STAGE_H, lane, wm, wn);
        if (t + 2 < kt)
            ld_stage(smbase + ((t + 2) % 3) * 2 * STAGE_H,
                     A, lda, B, ldb, m0, n0, (t + 2) * BKT, tid);
        cpcommit();
    }
    cpwait<0>();
}

// ---------------------------------------------------------------------------
// fp32 SIMT kpre (runs once): c[s] = [x|u] @ W_s[:,256:]^T + bias_s
// ---------------------------------------------------------------------------
__device__ __forceinline__ void mm_compute(float acc[8][4],
    const float As[BK][BM + 4], const float Bs[BK][BN], int tx, int ty)
{
#pragma unroll
    for (int kk = 0; kk < BK; kk++) {
        float4 a0 = *reinterpret_cast<const float4*>(&As[kk][ty * 8]);
        float4 a1 = *reinterpret_cast<const float4*>(&As[kk][ty * 8 + 4]);
        float4 b  = *reinterpret_cast<const float4*>(&Bs[kk][tx * 4]);
        float av[8] = {a0.x, a0.y, a0.z, a0.w, a1.x, a1.y, a1.z, a1.w};
        float bv[4] = {b.x, b.y, b.z, b.w};
#pragma unroll
        for (int i = 0; i < 8; i++)
#pragma unroll
            for (int j = 0; j < 4; j++)
                acc[i][j] = fmaf(av[i], bv[j], acc[i][j]);
    }
}
__device__ __forceinline__ void st_nt(float As[BK][BM + 4], float Bs[BK][BN],
                                      int r, int c, float4 va0, float4 va1, float4 vb)
{
    As[c + 0][r] = va0.x; As[c + 1][r] = va0.y; As[c + 2][r] = va0.z; As[c + 3][r] = va0.w;
    As[c + 0][r + 64] = va1.x; As[c + 1][r + 64] = va1.y; As[c + 2][r + 64] = va1.z; As[c + 3][r + 64] = va1.w;
    Bs[c + 0][r] = vb.x; Bs[c + 1][r] = vb.y; Bs[c + 2][r] = vb.z; Bs[c + 3][r] = vb.w;
}

__global__ void __launch_bounds__(NTHR) kpre(
    const float* __restrict__ x, const float* __restrict__ u,
    const float* __restrict__ W_in, const float* __restrict__ b_in,
    const float* __restrict__ Wxs, const float* __restrict__ bs)
{
    __shared__ float As[2][BK][BM + 4];
    __shared__ float Bs[2][BK][BN];
    const int tid = threadIdx.x, tx = tid & 15, ty = tid >> 4;
    const int m0 = blockIdx.y * BM, n0 = blockIdx.x * BN;
    const int s = blockIdx.z;
    const float* W    = (s == 0) ? W_in : Wxs + (size_t)(s - 1) * HH;
    const float* bias = (s == 0) ? b_in : bs + (size_t)(s - 1) * Hd;
    float* Out = g_buf + O_C + (size_t)s * BH;

    float acc[8][4];
#pragma unroll
    for (int i = 0; i < 8; i++)
#pragma unroll
        for (int j = 0; j < 4; j++) acc[i][j] = 0.f;

    const int r = tid >> 2;
    const int c = (tid & 3) * 4;
    const int kt = 576 / BK;
    const float* Bp = W + (size_t)(n0 + r) * Hd + 256 + c;

    float4 va0, va1, vb;
    va0 = *reinterpret_cast<const float4*>(&x[(size_t)(m0 + r) * 512 + c]);
    va1 = *reinterpret_cast<const float4*>(&x[(size_t)(m0 + r + 64) * 512 + c]);
    vb  = *reinterpret_cast<const float4*>(Bp);
    __syncthreads();
    st_nt(As[0], Bs[0], r, c, va0, va1, vb);
    __syncthreads();

    for (int t = 0; t < kt; t++) {
        int buf = t & 1;
        if (t + 1 < kt) {
            int k = (t + 1) * BK + c;
            if (k < 512) {
                va0 = *reinterpret_cast<const float4*>(&x[(size_t)(m0 + r) * 512 + k]);
                va1 = *reinterpret_cast<const float4*>(&x[(size_t)(m0 + r + 64) * 512 + k]);
            } else {
                va0 = *reinterpret_cast<const float4*>(&u[(size_t)(m0 + r) * 64 + (k - 512)]);
                va1 = *reinterpret_cast<const float4*>(&u[(size_t)(m0 + r + 64) * 64 + (k - 512)]);
            }
            vb = *reinterpret_cast<const float4*>(Bp + (t + 1) * BK);
        }
        mm_compute(acc, As[buf], Bs[buf], tx, ty);
        if (t + 1 < kt) st_nt(As[buf ^ 1], Bs[buf ^ 1], r, c, va0, va1, vb);
        __syncthreads();
    }

    const float4 b4 = *reinterpret_cast<const float4*>(&bias[n0 + tx * 4]);
#pragma unroll
    for (int i = 0; i < 8; i++) {
        int m = m0 + ty * 8 + i;
        float4 o;
        o.x = acc[i][0] + b4.x; o.y = acc[i][1] + b4.y;
        o.z = acc[i][2] + b4.z; o.w = acc[i][3] + b4.w;
        *reinterpret_cast<float4*>(&Out[(size_t)m * Hd + n0 + tx * 4]) = o;
    }
}

// ---------------------------------------------------------------------------
// Prep: BCAT=[sp(Wz)*32 | Wx_z*32] (rows of 1088), SWZT (unscaled, transp),
// WXZT/WINZ/WINZT (*32), z-tails of H buffers zeroed, state init.
// ---------------------------------------------------------------------------
__global__ void kprep(const float* __restrict__ Wzs, const float* __restrict__ wz_out,
                      const float* __restrict__ W_in, const float* __restrict__ Wxs,
                      float* __restrict__ Z)
{
    __half* hf = g_hf;
    float* SWZO = g_buf + O_SWZO;
    float* Mm = g_buf + O_M;
    float* Vv = g_buf + O_V;
    const int n = 3 * HH;
    for (int i = blockIdx.x * blockDim.x + threadIdx.x; i < n;
         i += gridDim.x * blockDim.x) {
        int l = i / HH, o = i - l * HH;
        int r = o / Hd, c = o - r * Hd;
        float w = sp_(Wzs[i]);
        hf[OB_BC + (size_t)l * (832ull * HW) + (size_t)r * HW + c] = __float2half_rn(w * SCL);
        hf[OB_SWZT + (size_t)l * HH + (size_t)c * Hd + r] = __float2half_rn(w);
        if (c < Zd) {
            float wx = Wxs[i] * SCL;
            hf[OB_BC + (size_t)l * (832ull * HW) + (size_t)r * HW + Hd + c] = __float2half_rn(wx);
            hf[OB_WXZT + (size_t)l * (Zd * Hd) + (size_t)c * Hd + r] = __float2half_rn(wx);
            if (l == 0) {
                float wi = W_in[o] * SCL;
                hf[OB_WINZ + (size_t)r * Zd + c] = __float2half_rn(wi);
                hf[OB_WINZT + (size_t)c * Hd + r] = __float2half_rn(wi);
            }
        }
        if (i < Hd) SWZO[i] = sp_(wz_out[i]);
        if (i < BZ) {
            Z[i] = 0.f; Mm[i] = 0.f; Vv[i] = 0.f;
            hf[OB_Z + i] = __float2half_rn(0.f);
            int m = i / Zd, j = i - m * Zd;
            size_t tb = (size_t)m * HW + Hd + j;
            hf[OB_H + tb] = __float2half_rn(0.f);
            hf[OB_H + BHW + tb] = __float2half_rn(0.f);
            hf[OB_H + 2ull * BHW + tb] = __float2half_rn(0.f);
        }
    }
}

// ---------------------------------------------------------------------------
// Forward: MODE 0 input layer (A=Zq K=256), MODE 1/2 hidden (A=[h|z] K=1088,
// B=BCAT). MODE 1 stores h x2^-5 into [.,0:832] of next H; MODE 2 stores d3
// unscaled into DA (stride Hd).
// ---------------------------------------------------------------------------
template<int MODE>
__global__ void __launch_bounds__(NTHR, 2) kfwd(
    const __half* __restrict__ A1, const __half* __restrict__ B1,
    const float* __restrict__ C0, __half* __restrict__ O)
{
    extern __shared__ __align__(16) char dsm[];
    uint32_t smbase = (uint32_t)__cvta_generic_to_shared(dsm);
    const int tid = threadIdx.x, lane = tid & 31, wid = tid >> 5;
    const int wm = (wid >> 1) * 32, wn = (wid & 1) * 32;
    const int m0 = blockIdx.y * BM, n0 = blockIdx.x * BN;

    float acc[2][4][4];
#pragma unroll
    for (int a = 0; a < 2; a++)
#pragma unroll
        for (int b = 0; b < 4; b++)
#pragma unroll
            for (int d = 0; d < 4; d++) acc[a][b][d] = 0.f;

    const int lda = (MODE == 0) ? Zd : HW;
    const int kt  = (MODE == 0) ? (Zd / BKT) : (HW / BKT);
    gemm_tn(acc, smbase, A1, lda, B1, lda, kt, m0, n0, tid, lane, wm, wn);

    const int ostr = (MODE == 2) ? Hd : HW;
    const int l4 = lane >> 2, l2 = (lane & 3) * 2;
#pragma unroll
    for (int mi = 0; mi < 2; mi++)
#pragma unroll
    for (int ni = 0; ni < 4; ni++) {
        int mA = m0 + wm + mi * 16 + l4;
        int n  = n0 + wn + ni * 8 + l2;
        size_t iCA = (size_t)mA * Hd + n, iCB = iCA + 8ull * Hd;
        size_t iOA = (size_t)mA * ostr + n, iOB = iOA + 8ull * ostr;
        float2 cA = *(const float2*)(C0 + iCA);
        float2 cB = *(const float2*)(C0 + iCB);
        float v0 = acc[mi][ni][0] + cA.x, v1 = acc[mi][ni][1] + cA.y;
        float v2 = acc[mi][ni][2] + cB.x, v3 = acc[mi][ni][3] + cB.y;
        if (MODE == 2) {
            const float* SWZO = g_buf + O_SWZO;
            float2 s2 = *(const float2*)(SWZO + n);
            v0 = s2.x * sig_(v0); v1 = s2.y * sig_(v1);
            v2 = s2.x * sig_(v2); v3 = s2.y * sig_(v3);
            *(__half2*)(O + iOA) = __floats2half2_rn(v0, v1);
            *(__half2*)(O + iOB) = __floats2half2_rn(v2, v3);
        } else {
            v0 = sp_(v0); v1 = sp_(v1); v2 = sp_(v2); v3 = sp_(v3);
            *(__half2*)(O + iOA) = __floats2half2_rn(v0 * ISCL, v1 * ISCL);
            *(__half2*)(O + iOB) = __floats2half2_rn(v2 * ISCL, v3 * ISCL);
        }
    }
}

// ---------------------------------------------------------------------------
// Backward hidden layer. D stride Hd; Hp (activations) stride HW.
// ---------------------------------------------------------------------------
template<bool FIRSTG>
__global__ void __launch_bounds__(NTHR, 2) kbwd(
    const __half* __restrict__ D,
    const __half* __restrict__ ST, const __half* __restrict__ XT,
    const __half* __restrict__ Hp, __half* __restrict__ O,
    const float* __restrict__ wx_out, float rs, float gs)
{
    extern __shared__ __align__(16) char dsm[];
    uint32_t smbase = (uint32_t)__cvta_generic_to_shared(dsm);
    const int tid = threadIdx.x, lane = tid & 31, wid = tid >> 5;
    const int wm = (wid >> 1) * 32, wn = (wid & 1) * 32;
    const int m0 = blockIdx.y * BM, n0 = blockIdx.x * BN;
    const bool gpath = (n0 >= Hd);
    const int nb = gpath ? (n0 - Hd) : n0;

    float acc[2][4][4];
#pragma unroll
    for (int a = 0; a < 2; a++)
#pragma unroll
        for (int b = 0; b < 4; b++)
#pragma unroll
            for (int d = 0; d < 4; d++) acc[a][b][d] = 0.f;

    gemm_tn(acc, smbase, D, Hd, gpath ? XT : ST, Hd, Hd / BKT,
            m0, nb, tid, lane, wm, wn);

    const int l4 = lane >> 2, l2 = (lane & 3) * 2;
    if (!gpath) {
#pragma unroll
        for (int mi = 0; mi < 2; mi++)
#pragma unroll
        for (int ni = 0; ni < 4; ni++) {
            int mA = m0 + wm + mi * 16 + l4;
            int n  = n0 + wn + ni * 8 + l2;
            size_t iA = (size_t)mA * Hd + n, iB = iA + 8ull * Hd;
            size_t hA = (size_t)mA * HW + n, hB = hA + 8ull * HW;
            __half2 h2A = *(const __half2*)(Hp + hA);
            __half2 h2B = *(const __half2*)(Hp + hB);
            float d0 = acc[mi][ni][0] * sig_from_h(__half2float(h2A.x) * SCL) * rs;
            float d1 = acc[mi][ni][1] * sig_from_h(__half2float(h2A.y) * SCL) * rs;
            float d2 = acc[mi][ni][2] * sig_from_h(__half2float(h2B.x) * SCL) * rs;
            float d3 = acc[mi][ni][3] * sig_from_h(__half2float(h2B.y) * SCL) * rs;
            *(__half2*)(O + iA) = __floats2half2_rn(d0, d1);
            *(__half2*)(O + iB) = __floats2half2_rn(d2, d3);
        }
    } else {
        float* G = g_buf + O_G;
#pragma unroll
        for (int mi = 0; mi < 2; mi++)
#pragma unroll
        for (int ni = 0; ni < 4; ni++) {
            int mA = m0 + wm + mi * 16 + l4;
            int np = nb + wn + ni * 8 + l2;
            size_t gA = (size_t)mA * Zd + np, gB = gA + 8ull * Zd;
            float2 bA, bB;
            if (FIRSTG) {
                float2 w2 = *(const float2*)(wx_out + np);
                bA = w2; bB = w2;
            } else {
                bA = *(const float2*)(G + gA);
                bB = *(const float2*)(G + gB);
            }
            float2 oA, oB;
            oA.x = bA.x + acc[mi][ni][0] * gs; oA.y = bA.y + acc[mi][ni][1] * gs;
            oB.x = bB.x + acc[mi][ni][2] * gs; oB.y = bB.y + acc[mi][ni][3] * gs;
            *(float2*)(G + gA) = oA;
            *(float2*)(G + gB) = oB;
        }
    }
}

// ---------------------------------------------------------------------------
// Final backward + Adam: g = G + acc*gs; z fp32 master + fp16 x2^-5 copies
// into Zq AND the z-tails of H0/H1/H2 (for next step's concatenated fwd).
// ---------------------------------------------------------------------------
__global__ void __launch_bounds__(NTHR, 2) kbwdin(
    const __half* __restrict__ D, const __half* __restrict__ WT,
    float* __restrict__ Z, __half* __restrict__ Zq, __half* __restrict__ Hb,
    float bc1, float bc2, float gs)
{
    extern __shared__ __align__(16) char dsm[];
    uint32_t smbase = (uint32_t)__cvta_generic_to_shared(dsm);
    const int tid = threadIdx.x, lane = tid & 31, wid = tid >> 5;
    const int wm = (wid >> 1) * 32, wn = (wid & 1) * 32;
    const int m0 = blockIdx.y * BM, n0 = blockIdx.x * BN;

    float acc[2][4][4];
#pragma unroll
    for (int a = 0; a < 2; a++)
#pragma unroll
        for (int b = 0; b < 4; b++)
#pragma unroll
            for (int d = 0; d < 4; d++) acc[a][b][d] = 0.f;

    gemm_tn(acc, smbase, D, Hd, WT, Hd, Hd / BKT, m0, n0, tid, lane, wm, wn);

    const float* G = g_buf + O_G;
    float* Mm = g_buf + O_M;
    float* Vv = g_buf + O_V;
    const int l4 = lane >> 2, l2 = (lane & 3) * 2;
#pragma unroll
    for (int mi = 0; mi < 2; mi++)
#pragma unroll
    for (int ni = 0; ni < 4; ni++) {
        int mA = m0 + wm + mi * 16 + l4;
        int np = n0 + wn + ni * 8 + l2;
#pragma unroll
        for (int hh = 0; hh < 2; hh++) {
            int mrow = mA + hh * 8;
            size_t id = (size_t)mrow * Zd + np;
            float g0 = G[id]     + acc[mi][ni][hh * 2 + 0] * gs;
            float g1 = G[id + 1] + acc[mi][ni][hh * 2 + 1] * gs;
            float2 m2 = *(const float2*)(Mm + id);
            float2 v2 = *(const float2*)(Vv + id);
            float nm0 = 0.9f * m2.x + 0.1f * g0;
            float nm1 = 0.9f * m2.y + 0.1f * g1;
            float nv0 = 0.999f * v2.x + 0.001f * g0 * g0;
            float nv1 = 0.999f * v2.y + 0.001f * g1 * g1;
            *(float2*)(Mm + id) = make_float2(nm0, nm1);
            *(float2*)(Vv + id) = make_float2(nv0, nv1);
            float2 z2 = *(const float2*)(Z + id);
            z2.x -= 0.01f * (nm0 * bc1) / (sqrtf(nv0 * bc2) + 1e-8f);
            z2.y -= 0.01f * (nm1 * bc1) / (sqrtf(nv1 * bc2) + 1e-8f);
            *(float2*)(Z + id) = z2;
            __half2 zq = __floats2half2_rn(z2.x * ISCL, z2.y * ISCL);
            *(__half2*)(Zq + id) = zq;
            size_t tb = (size_t)mrow * HW + Hd + np;
            *(__half2*)(Hb + tb) = zq;
            *(__half2*)(Hb + BHW + tb) = zq;
            *(__half2*)(Hb + 2ull * BHW + tb) = zq;
        }
    }
}

// ---------------------------------------------------------------------------
// Host driver
// ---------------------------------------------------------------------------
extern "C" void kernel_launch(void* const* d_in, const int* in_sizes, int n_in,
                              void* d_out, int out_size)
{
    (void)in_sizes; (void)n_in; (void)out_size;
    const float* x      = (const float*)d_in[0];
    const float* u      = (const float*)d_in[1];
    const float* W_in   = (const float*)d_in[2];
    const float* b_in   = (const float*)d_in[3];
    const float* Wzs    = (const float*)d_in[4];
    const float* Wxs    = (const float*)d_in[5];
    const float* bs     = (const float*)d_in[6];
    const float* wz_out = (const float*)d_in[7];
    const float* wx_out = (const float*)d_in[8];
    float* z = (float*)d_out;

    float* buf = nullptr;
    { void* p = nullptr; cudaGetSymbolAddress(&p, g_buf); buf = (float*)p; }
    __half* hb = nullptr;
    { void* p = nullptr; cudaGetSymbolAddress(&p, g_hf); hb = (__half*)p; }

    float* C = buf + O_C;

    static bool attr_done = false;
    if (!attr_done) {
        cudaFuncSetAttribute(kfwd<0>, cudaFuncAttributeMaxDynamicSharedMemorySize, SMEM_BYTES);
        cudaFuncSetAttribute(kfwd<1>, cudaFuncAttributeMaxDynamicSharedMemorySize, SMEM_BYTES);
        cudaFuncSetAttribute(kfwd<2>, cudaFuncAttributeMaxDynamicSharedMemorySize, SMEM_BYTES);
        cudaFuncSetAttribute(kbwd<true>,  cudaFuncAttributeMaxDynamicSharedMemorySize, SMEM_BYTES);
        cudaFuncSetAttribute(kbwd<false>, cudaFuncAttributeMaxDynamicSharedMemorySize, SMEM_BYTES);
        cudaFuncSetAttribute(kbwdin, cudaFuncAttributeMaxDynamicSharedMemorySize, SMEM_BYTES);
        attr_done = true;
    }

    kprep<<<2048, 512>>>(Wzs, wz_out, W_in, Wxs, z);
    kpre<<<dim3(Hd / BN, Bsz / BM, 4), NTHR>>>(x, u, W_in, b_in, Wxs, bs);

    const dim3 gF(Hd / BN, Bsz / BM);            // 13 x 32
    const dim3 gB((Hd + Zd) / BN, Bsz / BM);     // 17 x 32
    const dim3 gI(Zd / BN, Bsz / BM);            // 4 x 32
    const dim3 blk(NTHR);

    __half *Zq = hb + OB_Z;
    __half *DA = hb + OB_DA, *DB = hb + OB_DB;
    __half *Hb = hb + OB_H;

    const float RS_32 = 1.0f;
    const float RS_21 = 0.0625f;            // 2^-4
    const float RS_10 = 0.001953125f;       // 2^-9
    const float GS_3  = 0.03125f;           // 2^-5
    const float GS_2  = 0.03125f;           // 2^-5
    const float GS_1  = 0.5f;               // 2^-1
    const float GS_0  = 256.0f;             // 2^8

    for (int t = 0; t < NSTEPS; t++) {
        kfwd<0><<<gF, blk, SMEM_BYTES>>>(Zq, hb + OB_WINZ, C, Hb);
        kfwd<1><<<gF, blk, SMEM_BYTES>>>(
            Hb, hb + OB_BC, C + 1ull * BH, Hb + BHW);
        kfwd<1><<<gF, blk, SMEM_BYTES>>>(
            Hb + BHW, hb + OB_BC + 832ull * HW, C + 2ull * BH, Hb + 2ull * BHW);
        kfwd<2><<<gF, blk, SMEM_BYTES>>>(
            Hb + 2ull * BHW, hb + OB_BC + 2ull * 832ull * HW, C + 3ull * BH, DA);
        kbwd<true><<<gB, blk, SMEM_BYTES>>>(
            DA, hb + OB_SWZT + 2ull * HH, hb + OB_WXZT + 2ull * (Zd * Hd),
            Hb + 2ull * BHW, DB, wx_out, RS_32, GS_3);
        kbwd<false><<<gB, blk, SMEM_BYTES>>>(
            DB, hb + OB_SWZT + 1ull * HH, hb + OB_WXZT + 1ull * (Zd * Hd),
            Hb + BHW, DA, wx_out, RS_21, GS_2);
        kbwd<false><<<gB, blk, SMEM_BYTES>>>(
            DA, hb + OB_SWZT, hb + OB_WXZT,
            Hb, DB, wx_out, RS_10, GS_1);
        double p1 = 1.0, p2 = 1.0;
        for (int q = 0; q <= t; q++) { p1 *= 0.9; p2 *= 0.999; }
        float bc1 = (float)(1.0 / (1.0 - p1));
        float bc2 = (float)(1.0 / (1.0 - p2));
        kbwdin<<<gI, blk, SMEM_BYTES>>>(
            DB, hb + OB_WINZT, z, Zq, Hb, bc1, bc2, GS_0);
    }
}

// round 15
// speedup vs baseline: 1.0004x; 1.0004x over previous
#include <cuda_runtime.h>
#include <cuda_fp16.h>
#include <math.h>
#include <stdint.h>

// ---------------------------------------------------------------------------
// KoopmanPhiICNN encode, R15: R14 (single-pass fp16, BKT=64, K-concat fwd)
// with CTA tile halved to 64x64 (128 threads, 4 warps, warp tile 32x32)
// -> 4 CTAs/SM, halved wave-quantization tail.
// ---------------------------------------------------------------------------

#define Bsz 4096
#define Hd  832
#define Zd  256
#define HW  1088
#define BH  (Bsz*Hd)
#define BHW (4096ull*1088ull)
#define HH  (Hd*Hd)
#define BZ  (Bsz*Zd)
#define NSTEPS 64

#define BM 64
#define BN 64
#define BKT 64
#define BK 16
#define GT  128       // GEMM kernel threads (4 warps)
#define NTHR 256      // kpre threads
#define NSTAGE 3

#define SCL   32.0f
#define ISCL  0.03125f

// ---- fp32 scratch ----
#define O_SWZO 0ull
#define O_C    (O_SWZO + 1024ull)
#define O_G    (O_C + 4ull*BH)
#define O_M    (O_G + (unsigned long long)BZ)
#define O_V    (O_M + (unsigned long long)BZ)
#define TOTALF (O_V + (unsigned long long)BZ)
__device__ __align__(16) float g_buf[TOTALF];

// ---- fp16 scratch ----
#define SZ_WINZ  (832ull*256ull)
#define SZ_BC    (3ull*832ull*1088ull)
#define SZ_SWZ   (3ull*(unsigned long long)HH)
#define SZ_WXZ   (3ull*832ull*256ull)
#define OB_WINZ   0ull
#define OB_BC     (OB_WINZ + SZ_WINZ)
#define OB_SWZT   (OB_BC + SZ_BC)
#define OB_WXZT   (OB_SWZT + SZ_SWZ)
#define OB_WINZT  (OB_WXZT + SZ_WXZ)
#define OB_H      (OB_WINZT + SZ_WINZ)
#define OB_DA     (OB_H + 3ull*BHW)
#define OB_DB     (OB_DA + (unsigned long long)BH)
#define OB_Z      (OB_DB + (unsigned long long)BH)
#define TOTALH    (OB_Z + (unsigned long long)BZ)
__device__ __align__(16) __half g_hf[TOTALH];

__device__ __forceinline__ float sp_(float x) {
    return fmaxf(x, 0.f) + log1pf(expf(-fabsf(x)));
}
__device__ __forceinline__ float sig_(float x) { return 1.f / (1.f + expf(-x)); }
__device__ __forceinline__ float sig_from_h(float h) { return -expm1f(-h); }

// ---------------------------------------------------------------------------
// TN tensor-core GEMM core: C[64,64] += A[64,K]*B[64,K]^T, single fp16,
// K-stage 64 (rows 64 halves, stride SA=72, conflict-free ldsm).
// ---------------------------------------------------------------------------
#define SA 72
#define OFF_A  0
#define OFF_B  (64*SA)
#define STAGE_H ((64+64)*SA)                // 9216 halves = 18432 B
#define SMEM_BYTES (NSTAGE*2*STAGE_H)       // 55296 B -> 4 CTAs/SM

__device__ __forceinline__ void ldsm4(uint32_t* r, uint32_t addr) {
    asm volatile("ldmatrix.sync.aligned.m8n8.x4.shared.b16 {%0,%1,%2,%3}, [%4];\n"
        : "=r"(r[0]), "=r"(r[1]), "=r"(r[2]), "=r"(r[3]) : "r"(addr));
}
__device__ __forceinline__ void mmah(float* c, const uint32_t* a, uint32_t b0, uint32_t b1) {
    asm volatile("mma.sync.aligned.m16n8k16.row.col.f32.f16.f16.f32 "
        "{%0,%1,%2,%3},{%4,%5,%6,%7},{%8,%9},{%0,%1,%2,%3};\n"
        : "+f"(c[0]), "+f"(c[1]), "+f"(c[2]), "+f"(c[3])
        : "r"(a[0]), "r"(a[1]), "r"(a[2]), "r"(a[3]), "r"(b0), "r"(b1));
}
__device__ __forceinline__ void cp16(uint32_t dst, const void* src) {
    asm volatile("cp.async.cg.shared.global [%0], [%1], 16;\n" :: "r"(dst), "l"(src));
}
__device__ __forceinline__ void cpcommit() { asm volatile("cp.async.commit_group;\n"); }
template<int N> __device__ __forceinline__ void cpwait() {
    asm volatile("cp.async.wait_group %0;\n" :: "n"(N));
}

__device__ __forceinline__ void ld_stage(uint32_t smst,
    const __half* __restrict__ A, int lda,
    const __half* __restrict__ B, int ldb,
    int m0, int n0, int k0, int tid)
{
    // A: 64 rows x 8 chunks = 512, 4 per thread (128 thr)
#pragma unroll
    for (int h = 0; h < 4; h++) {
        int ch = tid + h * 128;
        int row = ch >> 3, kc = ch & 7;
        size_t go = (size_t)(m0 + row) * lda + k0 + kc * 8;
        uint32_t so = smst + 2 * (OFF_A + row * SA + kc * 8);
        cp16(so, A + go);
    }
    // B: 64 rows x 8 chunks = 512, 4 per thread
#pragma unroll
    for (int h = 0; h < 4; h++) {
        int ch = tid + h * 128;
        int row = ch >> 3, kc = ch & 7;
        size_t go = (size_t)(n0 + row) * ldb + k0 + kc * 8;
        uint32_t so = smst + 2 * (OFF_B + row * SA + kc * 8);
        cp16(so, B + go);
    }
}

__device__ __forceinline__ void compute_stage(float acc[2][4][4], uint32_t smst,
                                              int lane, int wm, int wn)
{
#pragma unroll
    for (int kk = 0; kk < 4; kk++) {
        const int k16 = kk * 16;
        uint32_t a0[4], a1[4];
        {
            int arow = lane & 15;
            int akoff = k16 + ((lane >> 4) << 3);
            uint32_t ad = smst + 2 * ((wm + arow) * SA + akoff);
            ldsm4(a0, ad);
            ldsm4(a1, ad + 2 * 16 * SA);
        }
        uint32_t b0[4], b1[4];
        {
            int brow = ((lane >> 4) << 3) + (lane & 7);
            int bkoff = k16 + (((lane >> 3) & 1) << 3);
            uint32_t bd = smst + 2 * (OFF_B + (wn + brow) * SA + bkoff);
            ldsm4(b0, bd);
            ldsm4(b1, bd + 2 * 16 * SA);
        }
#pragma unroll
        for (int mi = 0; mi < 2; mi++) {
            const uint32_t* Af = mi ? a1 : a0;
#pragma unroll
            for (int ni = 0; ni < 4; ni++) {
                const uint32_t* Bf = (ni < 2) ? b0 : b1;
                int h2 = (ni & 1) * 2;
                mmah(acc[mi][ni], Af, Bf[h2], Bf[h2 + 1]);
            }
        }
    }
}

__device__ __forceinline__ void gemm_tn(float acc[2][4][4], uint32_t smbase,
    const __half* A, int lda,
    const __half* B, int ldb,
    int kt, int m0, int n0, int tid, int lane, int wm, int wn)
{
    __syncthreads();
    ld_stage(smbase, A, lda, B, ldb, m0, n0, 0, tid);
    cpcommit();
    if (kt > 1) ld_stage(smbase + 2 * STAGE_H, A, lda, B, ldb, m0, n0, BKT, tid);
    cpcommit();

    for (int t = 0; t < kt; t++) {
        cpwait<1>();
        __syncthreads();
        compute_stage(acc, smbase + (t % 3) * 2 * STAGE_H, lane, wm, wn);
        if (t + 2 < kt)
            ld_stage(smbase + ((t + 2) % 3) * 2 * STAGE_H,
                     A, lda, B, ldb, m0, n0, (t + 2) * BKT, tid);
        cpcommit();
    }
    cpwait<0>();
}

// ---------------------------------------------------------------------------
// fp32 SIMT kpre (runs once): c[s] = [x|u] @ W_s[:,256:]^T + bias_s
// ---------------------------------------------------------------------------
#define PBM 128
__device__ __forceinline__ void mm_compute(float acc[8][4],
    const float As[BK][PBM + 4], const float Bs[BK][BN], int tx, int ty)
{
#pragma unroll
    for (int kk = 0; kk < BK; kk++) {
        float4 a0 = *reinterpret_cast<const float4*>(&As[kk][ty * 8]);
        float4 a1 = *reinterpret_cast<const float4*>(&As[kk][ty * 8 + 4]);
        float4 b  = *reinterpret_cast<const float4*>(&Bs[kk][tx * 4]);
        float av[8] = {a0.x, a0.y, a0.z, a0.w, a1.x, a1.y, a1.z, a1.w};
        float bv[4] = {b.x, b.y, b.z, b.w};
#pragma unroll
        for (int i = 0; i < 8; i++)
#pragma unroll
            for (int j = 0; j < 4; j++)
                acc[i][j] = fmaf(av[i], bv[j], acc[i][j]);
    }
}
__device__ __forceinline__ void st_nt(float As[BK][PBM + 4], float Bs[BK][BN],
                                      int r, int c, float4 va0, float4 va1, float4 vb)
{
    As[c + 0][r] = va0.x; As[c + 1][r] = va0.y; As[c + 2][r] = va0.z; As[c + 3][r] = va0.w;
    As[c + 0][r + 64] = va1.x; As[c + 1][r + 64] = va1.y; As[c + 2][r + 64] = va1.z; As[c + 3][r + 64] = va1.w;
    Bs[c + 0][r] = vb.x; Bs[c + 1][r] = vb.y; Bs[c + 2][r] = vb.z; Bs[c + 3][r] = vb.w;
}

__global__ void __launch_bounds__(NTHR) kpre(
    const float* __restrict__ x, const float* __restrict__ u,
    const float* __restrict__ W_in, const float* __restrict__ b_in,
    const float* __restrict__ Wxs, const float* __restrict__ bs)
{
    __shared__ float As[2][BK][PBM + 4];
    __shared__ float Bs[2][BK][BN];
    const int tid = threadIdx.x, tx = tid & 15, ty = tid >> 4;
    const int m0 = blockIdx.y * PBM, n0 = blockIdx.x * BN;
    const int s = blockIdx.z;
    const float* W    = (s == 0) ? W_in : Wxs + (size_t)(s - 1) * HH;
    const float* bias = (s == 0) ? b_in : bs + (size_t)(s - 1) * Hd;
    float* Out = g_buf + O_C + (size_t)s * BH;

    float acc[8][4];
#pragma unroll
    for (int i = 0; i < 8; i++)
#pragma unroll
        for (int j = 0; j < 4; j++) acc[i][j] = 0.f;

    const int r = tid >> 2;
    const int c = (tid & 3) * 4;
    const int kt = 576 / BK;
    const float* Bp = W + (size_t)(n0 + r) * Hd + 256 + c;

    float4 va0, va1, vb;
    va0 = *reinterpret_cast<const float4*>(&x[(size_t)(m0 + r) * 512 + c]);
    va1 = *reinterpret_cast<const float4*>(&x[(size_t)(m0 + r + 64) * 512 + c]);
    vb  = *reinterpret_cast<const float4*>(Bp);
    __syncthreads();
    st_nt(As[0], Bs[0], r, c, va0, va1, vb);
    __syncthreads();

    for (int t = 0; t < kt; t++) {
        int buf = t & 1;
        if (t + 1 < kt) {
            int k = (t + 1) * BK + c;
            if (k < 512) {
                va0 = *reinterpret_cast<const float4*>(&x[(size_t)(m0 + r) * 512 + k]);
                va1 = *reinterpret_cast<const float4*>(&x[(size_t)(m0 + r + 64) * 512 + k]);
            } else {
                va0 = *reinterpret_cast<const float4*>(&u[(size_t)(m0 + r) * 64 + (k - 512)]);
                va1 = *reinterpret_cast<const float4*>(&u[(size_t)(m0 + r + 64) * 64 + (k - 512)]);
            }
            vb = *reinterpret_cast<const float4*>(Bp + (t + 1) * BK);
        }
        mm_compute(acc, As[buf], Bs[buf], tx, ty);
        if (t + 1 < kt) st_nt(As[buf ^ 1], Bs[buf ^ 1], r, c, va0, va1, vb);
        __syncthreads();
    }

    const float4 b4 = *reinterpret_cast<const float4*>(&bias[n0 + tx * 4]);
#pragma unroll
    for (int i = 0; i < 8; i++) {
        int m = m0 + ty * 8 + i;
        float4 o;
        o.x = acc[i][0] + b4.x; o.y = acc[i][1] + b4.y;
        o.z = acc[i][2] + b4.z; o.w = acc[i][3] + b4.w;
        *reinterpret_cast<float4*>(&Out[(size_t)m * Hd + n0 + tx * 4]) = o;
    }
}

// ---------------------------------------------------------------------------
// Prep: BCAT=[sp(Wz)*32 | Wx_z*32], SWZT (unscaled, transp), WXZT/WINZ/WINZT
// (*32), z-tails of H buffers zeroed, state init.
// ---------------------------------------------------------------------------
__global__ void kprep(const float* __restrict__ Wzs, const float* __restrict__ wz_out,
                      const float* __restrict__ W_in, const float* __restrict__ Wxs,
                      float* __restrict__ Z)
{
    __half* hf = g_hf;
    float* SWZO = g_buf + O_SWZO;
    float* Mm = g_buf + O_M;
    float* Vv = g_buf + O_V;
    const int n = 3 * HH;
    for (int i = blockIdx.x * blockDim.x + threadIdx.x; i < n;
         i += gridDim.x * blockDim.x) {
        int l = i / HH, o = i - l * HH;
        int r = o / Hd, c = o - r * Hd;
        float w = sp_(Wzs[i]);
        hf[OB_BC + (size_t)l * (832ull * HW) + (size_t)r * HW + c] = __float2half_rn(w * SCL);
        hf[OB_SWZT + (size_t)l * HH + (size_t)c * Hd + r] = __float2half_rn(w);
        if (c < Zd) {
            float wx = Wxs[i] * SCL;
            hf[OB_BC + (size_t)l * (832ull * HW) + (size_t)r * HW + Hd + c] = __float2half_rn(wx);
            hf[OB_WXZT + (size_t)l * (Zd * Hd) + (size_t)c * Hd + r] = __float2half_rn(wx);
            if (l == 0) {
                float wi = W_in[o] * SCL;
                hf[OB_WINZ + (size_t)r * Zd + c] = __float2half_rn(wi);
                hf[OB_WINZT + (size_t)c * Hd + r] = __float2half_rn(wi);
            }
        }
        if (i < Hd) SWZO[i] = sp_(wz_out[i]);
        if (i < BZ) {
            Z[i] = 0.f; Mm[i] = 0.f; Vv[i] = 0.f;
            hf[OB_Z + i] = __float2half_rn(0.f);
            int m = i / Zd, j = i - m * Zd;
            size_t tb = (size_t)m * HW + Hd + j;
            hf[OB_H + tb] = __float2half_rn(0.f);
            hf[OB_H + BHW + tb] = __float2half_rn(0.f);
            hf[OB_H + 2ull * BHW + tb] = __float2half_rn(0.f);
        }
    }
}

// ---------------------------------------------------------------------------
// Forward: MODE 0 input (A=Zq K=256), MODE 1/2 hidden (A=[h|z] K=1088, B=BCAT)
// ---------------------------------------------------------------------------
template<int MODE>
__global__ void __launch_bounds__(GT, 4) kfwd(
    const __half* __restrict__ A1, const __half* __restrict__ B1,
    const float* __restrict__ C0, __half* __restrict__ O)
{
    extern __shared__ __align__(16) char dsm[];
    uint32_t smbase = (uint32_t)__cvta_generic_to_shared(dsm);
    const int tid = threadIdx.x, lane = tid & 31, wid = tid >> 5;
    const int wm = (wid >> 1) * 32, wn = (wid & 1) * 32;
    const int m0 = blockIdx.y * BM, n0 = blockIdx.x * BN;

    float acc[2][4][4];
#pragma unroll
    for (int a = 0; a < 2; a++)
#pragma unroll
        for (int b = 0; b < 4; b++)
#pragma unroll
            for (int d = 0; d < 4; d++) acc[a][b][d] = 0.f;

    const int lda = (MODE == 0) ? Zd : HW;
    const int kt  = (MODE == 0) ? (Zd / BKT) : (HW / BKT);
    gemm_tn(acc, smbase, A1, lda, B1, lda, kt, m0, n0, tid, lane, wm, wn);

    const int ostr = (MODE == 2) ? Hd : HW;
    const int l4 = lane >> 2, l2 = (lane & 3) * 2;
#pragma unroll
    for (int mi = 0; mi < 2; mi++)
#pragma unroll
    for (int ni = 0; ni < 4; ni++) {
        int mA = m0 + wm + mi * 16 + l4;
        int n  = n0 + wn + ni * 8 + l2;
        size_t iCA = (size_t)mA * Hd + n, iCB = iCA + 8ull * Hd;
        size_t iOA = (size_t)mA * ostr + n, iOB = iOA + 8ull * ostr;
        float2 cA = *(const float2*)(C0 + iCA);
        float2 cB = *(const float2*)(C0 + iCB);
        float v0 = acc[mi][ni][0] + cA.x, v1 = acc[mi][ni][1] + cA.y;
        float v2 = acc[mi][ni][2] + cB.x, v3 = acc[mi][ni][3] + cB.y;
        if (MODE == 2) {
            const float* SWZO = g_buf + O_SWZO;
            float2 s2 = *(const float2*)(SWZO + n);
            v0 = s2.x * sig_(v0); v1 = s2.y * sig_(v1);
            v2 = s2.x * sig_(v2); v3 = s2.y * sig_(v3);
            *(__half2*)(O + iOA) = __floats2half2_rn(v0, v1);
            *(__half2*)(O + iOB) = __floats2half2_rn(v2, v3);
        } else {
            v0 = sp_(v0); v1 = sp_(v1); v2 = sp_(v2); v3 = sp_(v3);
            *(__half2*)(O + iOA) = __floats2half2_rn(v0 * ISCL, v1 * ISCL);
            *(__half2*)(O + iOB) = __floats2half2_rn(v2 * ISCL, v3 * ISCL);
        }
    }
}

// ---------------------------------------------------------------------------
// Backward hidden layer. D stride Hd; Hp (activations) stride HW.
// ---------------------------------------------------------------------------
template<bool FIRSTG>
__global__ void __launch_bounds__(GT, 4) kbwd(
    const __half* __restrict__ D,
    const __half* __restrict__ ST, const __half* __restrict__ XT,
    const __half* __restrict__ Hp, __half* __restrict__ O,
    const float* __restrict__ wx_out, float rs, float gs)
{
    extern __shared__ __align__(16) char dsm[];
    uint32_t smbase = (uint32_t)__cvta_generic_to_shared(dsm);
    const int tid = threadIdx.x, lane = tid & 31, wid = tid >> 5;
    const int wm = (wid >> 1) * 32, wn = (wid & 1) * 32;
    const int m0 = blockIdx.y * BM, n0 = blockIdx.x * BN;
    const bool gpath = (n0 >= Hd);
    const int nb = gpath ? (n0 - Hd) : n0;

    float acc[2][4][4];
#pragma unroll
    for (int a = 0; a < 2; a++)
#pragma unroll
        for (int b = 0; b < 4; b++)
#pragma unroll
            for (int d = 0; d < 4; d++) acc[a][b][d] = 0.f;

    gemm_tn(acc, smbase, D, Hd, gpath ? XT : ST, Hd, Hd / BKT,
            m0, nb, tid, lane, wm, wn);

    const int l4 = lane >> 2, l2 = (lane & 3) * 2;
    if (!gpath) {
#pragma unroll
        for (int mi = 0; mi < 2; mi++)
#pragma unroll
        for (int ni = 0; ni < 4; ni++) {
            int mA = m0 + wm + mi * 16 + l4;
            int n  = n0 + wn + ni * 8 + l2;
            size_t iA = (size_t)mA * Hd + n, iB = iA + 8ull * Hd;
            size_t hA = (size_t)mA * HW + n, hB = hA + 8ull * HW;
            __half2 h2A = *(const __half2*)(Hp + hA);
            __half2 h2B = *(const __half2*)(Hp + hB);
            float d0 = acc[mi][ni][0] * sig_from_h(__half2float(h2A.x) * SCL) * rs;
            float d1 = acc[mi][ni][1] * sig_from_h(__half2float(h2A.y) * SCL) * rs;
            float d2 = acc[mi][ni][2] * sig_from_h(__half2float(h2B.x) * SCL) * rs;
            float d3 = acc[mi][ni][3] * sig_from_h(__half2float(h2B.y) * SCL) * rs;
            *(__half2*)(O + iA) = __floats2half2_rn(d0, d1);
            *(__half2*)(O + iB) = __floats2half2_rn(d2, d3);
        }
    } else {
        float* G = g_buf + O_G;
#pragma unroll
        for (int mi = 0; mi < 2; mi++)
#pragma unroll
        for (int ni = 0; ni < 4; ni++) {
            int mA = m0 + wm + mi * 16 + l4;
            int np = nb + wn + ni * 8 + l2;
            size_t gA = (size_t)mA * Zd + np, gB = gA + 8ull * Zd;
            float2 bA, bB;
            if (FIRSTG) {
                float2 w2 = *(const float2*)(wx_out + np);
                bA = w2; bB = w2;
            } else {
                bA = *(const float2*)(G + gA);
                bB = *(const float2*)(G + gB);
            }
            float2 oA, oB;
            oA.x = bA.x + acc[mi][ni][0] * gs; oA.y = bA.y + acc[mi][ni][1] * gs;
            oB.x = bB.x + acc[mi][ni][2] * gs; oB.y = bB.y + acc[mi][ni][3] * gs;
            *(float2*)(G + gA) = oA;
            *(float2*)(G + gB) = oB;
        }
    }
}

// ---------------------------------------------------------------------------
// Final backward + Adam: g = G + acc*gs; z fp32 master + fp16 x2^-5 copies
// into Zq AND the z-tails of H0/H1/H2.
// ---------------------------------------------------------------------------
__global__ void __launch_bounds__(GT, 4) kbwdin(
    const __half* __restrict__ D, const __half* __restrict__ WT,
    float* __restrict__ Z, __half* __restrict__ Zq, __half* __restrict__ Hb,
    float bc1, float bc2, float gs)
{
    extern __shared__ __align__(16) char dsm[];
    uint32_t smbase = (uint32_t)__cvta_generic_to_shared(dsm);
    const int tid = threadIdx.x, lane = tid & 31, wid = tid >> 5;
    const int wm = (wid >> 1) * 32, wn = (wid & 1) * 32;
    const int m0 = blockIdx.y * BM, n0 = blockIdx.x * BN;

    float acc[2][4][4];
#pragma unroll
    for (int a = 0; a < 2; a++)
#pragma unroll
        for (int b = 0; b < 4; b++)
#pragma unroll
            for (int d = 0; d < 4; d++) acc[a][b][d] = 0.f;

    gemm_tn(acc, smbase, D, Hd, WT, Hd, Hd / BKT, m0, n0, tid, lane, wm, wn);

    const float* G = g_buf + O_G;
    float* Mm = g_buf + O_M;
    float* Vv = g_buf + O_V;
    const int l4 = lane >> 2, l2 = (lane & 3) * 2;
#pragma unroll
    for (int mi = 0; mi < 2; mi++)
#pragma unroll
    for (int ni = 0; ni < 4; ni++) {
        int mA = m0 + wm + mi * 16 + l4;
        int np = n0 + wn + ni * 8 + l2;
#pragma unroll
        for (int hh = 0; hh < 2; hh++) {
            int mrow = mA + hh * 8;
            size_t id = (size_t)mrow * Zd + np;
            float g0 = G[id]     + acc[mi][ni][hh * 2 + 0] * gs;
            float g1 = G[id + 1] + acc[mi][ni][hh * 2 + 1] * gs;
            float2 m2 = *(const float2*)(Mm + id);
            float2 v2 = *(const float2*)(Vv + id);
            float nm0 = 0.9f * m2.x + 0.1f * g0;
            float nm1 = 0.9f * m2.y + 0.1f * g1;
            float nv0 = 0.999f * v2.x + 0.001f * g0 * g0;
            float nv1 = 0.999f * v2.y + 0.001f * g1 * g1;
            *(float2*)(Mm + id) = make_float2(nm0, nm1);
            *(float2*)(Vv + id) = make_float2(nv0, nv1);
            float2 z2 = *(const float2*)(Z + id);
            z2.x -= 0.01f * (nm0 * bc1) / (sqrtf(nv0 * bc2) + 1e-8f);
            z2.y -= 0.01f * (nm1 * bc1) / (sqrtf(nv1 * bc2) + 1e-8f);
            *(float2*)(Z + id) = z2;
            __half2 zq = __floats2half2_rn(z2.x * ISCL, z2.y * ISCL);
            *(__half2*)(Zq + id) = zq;
            size_t tb = (size_t)mrow * HW + Hd + np;
            *(__half2*)(Hb + tb) = zq;
            *(__half2*)(Hb + BHW + tb) = zq;
            *(__half2*)(Hb + 2ull * BHW + tb) = zq;
        }
    }
}

// ---------------------------------------------------------------------------
// Host driver
// ---------------------------------------------------------------------------
extern "C" void kernel_launch(void* const* d_in, const int* in_sizes, int n_in,
                              void* d_out, int out_size)
{
    (void)in_sizes; (void)n_in; (void)out_size;
    const float* x      = (const float*)d_in[0];
    const float* u      = (const float*)d_in[1];
    const float* W_in   = (const float*)d_in[2];
    const float* b_in   = (const float*)d_in[3];
    const float* Wzs    = (const float*)d_in[4];
    const float* Wxs    = (const float*)d_in[5];
    const float* bs     = (const float*)d_in[6];
    const float* wz_out = (const float*)d_in[7];
    const float* wx_out = (const float*)d_in[8];
    float* z = (float*)d_out;

    float* buf = nullptr;
    { void* p = nullptr; cudaGetSymbolAddress(&p, g_buf); buf = (float*)p; }
    __half* hb = nullptr;
    { void* p = nullptr; cudaGetSymbolAddress(&p, g_hf); hb = (__half*)p; }

    float* C = buf + O_C;

    static bool attr_done = false;
    if (!attr_done) {
        cudaFuncSetAttribute(kfwd<0>, cudaFuncAttributeMaxDynamicSharedMemorySize, SMEM_BYTES);
        cudaFuncSetAttribute(kfwd<1>, cudaFuncAttributeMaxDynamicSharedMemorySize, SMEM_BYTES);
        cudaFuncSetAttribute(kfwd<2>, cudaFuncAttributeMaxDynamicSharedMemorySize, SMEM_BYTES);
        cudaFuncSetAttribute(kbwd<true>,  cudaFuncAttributeMaxDynamicSharedMemorySize, SMEM_BYTES);
        cudaFuncSetAttribute(kbwd<false>, cudaFuncAttributeMaxDynamicSharedMemorySize, SMEM_BYTES);
        cudaFuncSetAttribute(kbwdin, cudaFuncAttributeMaxDynamicSharedMemorySize, SMEM_BYTES);
        attr_done = true;
    }

    kprep<<<2048, 512>>>(Wzs, wz_out, W_in, Wxs, z);
    kpre<<<dim3(Hd / BN, Bsz / PBM, 4), NTHR>>>(x, u, W_in, b_in, Wxs, bs);

    const dim3 gF(Hd / BN, Bsz / BM);            // 13 x 64
    const dim3 gB((Hd + Zd) / BN, Bsz / BM);     // 17 x 64
    const dim3 gI(Zd / BN, Bsz / BM);            // 4 x 64
    const dim3 blk(GT);

    __half *Zq = hb + OB_Z;
    __half *DA = hb + OB_DA, *DB = hb + OB_DB;
    __half *Hb = hb + OB_H;

    const float RS_32 = 1.0f;
    const float RS_21 = 0.0625f;            // 2^-4
    const float RS_10 = 0.001953125f;       // 2^-9
    const float GS_3  = 0.03125f;           // 2^-5
    const float GS_2  = 0.03125f;           // 2^-5
    const float GS_1  = 0.5f;               // 2^-1
    const float GS_0  = 256.0f;             // 2^8

    for (int t = 0; t < NSTEPS; t++) {
        kfwd<0><<<gF, blk, SMEM_BYTES>>>(Zq, hb + OB_WINZ, C, Hb);
        kfwd<1><<<gF, blk, SMEM_BYTES>>>(
            Hb, hb + OB_BC, C + 1ull * BH, Hb + BHW);
        kfwd<1><<<gF, blk, SMEM_BYTES>>>(
            Hb + BHW, hb + OB_BC + 832ull * HW, C + 2ull * BH, Hb + 2ull * BHW);
        kfwd<2><<<gF, blk, SMEM_BYTES>>>(
            Hb + 2ull * BHW, hb + OB_BC + 2ull * 832ull * HW, C + 3ull * BH, DA);
        kbwd<true><<<gB, blk, SMEM_BYTES>>>(
            DA, hb + OB_SWZT + 2ull * HH, hb + OB_WXZT + 2ull * (Zd * Hd),
            Hb + 2ull * BHW, DB, wx_out, RS_32, GS_3);
        kbwd<false><<<gB, blk, SMEM_BYTES>>>(
            DB, hb + OB_SWZT + 1ull * HH, hb + OB_WXZT + 1ull * (Zd * Hd),
            Hb + BHW, DA, wx_out, RS_21, GS_2);
        kbwd<false><<<gB, blk, SMEM_BYTES>>>(
            DA, hb + OB_SWZT, hb + OB_WXZT,
            Hb, DB, wx_out, RS_10, GS_1);
        double p1 = 1.0, p2 = 1.0;
        for (int q = 0; q <= t; q++) { p1 *= 0.9; p2 *= 0.999; }
        float bc1 = (float)(1.0 / (1.0 - p1));
        float bc2 = (float)(1.0 / (1.0 - p2));
        kbwdin<<<gI, blk, SMEM_BYTES>>>(
            DB, hb + OB_WINZT, z, Zq, Hb, bc1, bc2, GS_0);
    }
}

// round 17
// speedup vs baseline: 1.0016x; 1.0013x over previous
#include <cuda_runtime.h>
#include <cuda_fp16.h>
#include <math.h>
#include <stdint.h>

// ---------------------------------------------------------------------------
// KoopmanPhiICNN encode, R17: R15 (single-pass fp16, BM=64, BKT=64, K-concat
// fwd, single stream) + register double-buffered ldsm pipelining: prefetch
// kk+1 fragments before issuing kk's mma block (hides smem latency).
// ---------------------------------------------------------------------------

#define Bsz 4096
#define Hd  832
#define Zd  256
#define HW  1088
#define BH  (Bsz*Hd)
#define BHW (4096ull*1088ull)
#define HH  (Hd*Hd)
#define BZ  (Bsz*Zd)
#define NSTEPS 64

#define BM 64
#define BN 64
#define BKT 64
#define BK 16
#define GT  128
#define NTHR 256
#define NSTAGE 3

#define SCL   32.0f
#define ISCL  0.03125f

// ---- fp32 scratch ----
#define O_SWZO 0ull
#define O_C    (O_SWZO + 1024ull)
#define O_G    (O_C + 4ull*BH)
#define O_M    (O_G + (unsigned long long)BZ)
#define O_V    (O_M + (unsigned long long)BZ)
#define TOTALF (O_V + (unsigned long long)BZ)
__device__ __align__(16) float g_buf[TOTALF];

// ---- fp16 scratch ----
#define SZ_WINZ  (832ull*256ull)
#define SZ_BC    (3ull*832ull*1088ull)
#define SZ_SWZ   (3ull*(unsigned long long)HH)
#define SZ_WXZ   (3ull*832ull*256ull)
#define OB_WINZ   0ull
#define OB_BC     (OB_WINZ + SZ_WINZ)
#define OB_SWZT   (OB_BC + SZ_BC)
#define OB_WXZT   (OB_SWZT + SZ_SWZ)
#define OB_WINZT  (OB_WXZT + SZ_WXZ)
#define OB_H      (OB_WINZT + SZ_WINZ)
#define OB_DA     (OB_H + 3ull*BHW)
#define OB_DB     (OB_DA + (unsigned long long)BH)
#define OB_Z      (OB_DB + (unsigned long long)BH)
#define TOTALH    (OB_Z + (unsigned long long)BZ)
__device__ __align__(16) __half g_hf[TOTALH];

__device__ __forceinline__ float sp_(float x) {
    return fmaxf(x, 0.f) + log1pf(expf(-fabsf(x)));
}
__device__ __forceinline__ float sig_(float x) { return 1.f / (1.f + expf(-x)); }
__device__ __forceinline__ float sig_from_h(float h) { return -expm1f(-h); }

// ---------------------------------------------------------------------------
// TN tensor-core GEMM core: C[64,64] += A[64,K]*B[64,K]^T, single fp16,
// K-stage 64 (rows 64 halves, stride SA=72, conflict-free ldsm).
// ---------------------------------------------------------------------------
#define SA 72
#define OFF_A  0
#define OFF_B  (64*SA)
#define STAGE_H ((64+64)*SA)                // 9216 halves = 18432 B
#define SMEM_BYTES (NSTAGE*2*STAGE_H)       // 55296 B -> 4 CTAs/SM

__device__ __forceinline__ void ldsm4(uint32_t* r, uint32_t addr) {
    asm volatile("ldmatrix.sync.aligned.m8n8.x4.shared.b16 {%0,%1,%2,%3}, [%4];\n"
        : "=r"(r[0]), "=r"(r[1]), "=r"(r[2]), "=r"(r[3]) : "r"(addr));
}
__device__ __forceinline__ void mmah(float* c, const uint32_t* a, uint32_t b0, uint32_t b1) {
    asm volatile("mma.sync.aligned.m16n8k16.row.col.f32.f16.f16.f32 "
        "{%0,%1,%2,%3},{%4,%5,%6,%7},{%8,%9},{%0,%1,%2,%3};\n"
        : "+f"(c[0]), "+f"(c[1]), "+f"(c[2]), "+f"(c[3])
        : "r"(a[0]), "r"(a[1]), "r"(a[2]), "r"(a[3]), "r"(b0), "r"(b1));
}
__device__ __forceinline__ void cp16(uint32_t dst, const void* src) {
    asm volatile("cp.async.cg.shared.global [%0], [%1], 16;\n" :: "r"(dst), "l"(src));
}
__device__ __forceinline__ void cpcommit() { asm volatile("cp.async.commit_group;\n"); }
template<int N> __device__ __forceinline__ void cpwait() {
    asm volatile("cp.async.wait_group %0;\n" :: "n"(N));
}

__device__ __forceinline__ void ld_stage(uint32_t smst,
    const __half* __restrict__ A, int lda,
    const __half* __restrict__ B, int ldb,
    int m0, int n0, int k0, int tid)
{
#pragma unroll
    for (int h = 0; h < 4; h++) {
        int ch = tid + h * 128;
        int row = ch >> 3, kc = ch & 7;
        size_t go = (size_t)(m0 + row) * lda + k0 + kc * 8;
        uint32_t so = smst + 2 * (OFF_A + row * SA + kc * 8);
        cp16(so, A + go);
    }
#pragma unroll
    for (int h = 0; h < 4; h++) {
        int ch = tid + h * 128;
        int row = ch >> 3, kc = ch & 7;
        size_t go = (size_t)(n0 + row) * ldb + k0 + kc * 8;
        uint32_t so = smst + 2 * (OFF_B + row * SA + kc * 8);
        cp16(so, B + go);
    }
}

// Register double-buffered compute: prefetch kk+1 ldsm before kk's mma block.
__device__ __forceinline__ void compute_stage(float acc[2][4][4], uint32_t smst,
                                              int lane, int wm, int wn)
{
    const int arow = lane & 15;
    const uint32_t abase = smst + 2 * ((wm + arow) * SA + ((lane >> 4) << 3));
    const int brow = ((lane >> 4) << 3) + (lane & 7);
    const uint32_t bbase = smst + 2 * (OFF_B + (wn + brow) * SA + (((lane >> 3) & 1) << 3));

    uint32_t af[2][8], bf[2][8];
    // load kk = 0 into buffer 0
    ldsm4(af[0] + 0, abase);
    ldsm4(af[0] + 4, abase + 2 * 16 * SA);
    ldsm4(bf[0] + 0, bbase);
    ldsm4(bf[0] + 4, bbase + 2 * 16 * SA);

#pragma unroll
    for (int kk = 0; kk < 4; kk++) {
        const int cur = kk & 1, nxt = cur ^ 1;
        if (kk < 3) {
            const uint32_t ao = (uint32_t)(2 * 16 * (kk + 1));
            ldsm4(af[nxt] + 0, abase + ao);
            ldsm4(af[nxt] + 4, abase + ao + 2 * 16 * SA);
            ldsm4(bf[nxt] + 0, bbase + ao);
            ldsm4(bf[nxt] + 4, bbase + ao + 2 * 16 * SA);
        }
#pragma unroll
        for (int mi = 0; mi < 2; mi++) {
            const uint32_t* Af = af[cur] + mi * 4;
#pragma unroll
            for (int ni = 0; ni < 4; ni++) {
                const uint32_t* Bf = (ni < 2) ? (bf[cur] + 0) : (bf[cur] + 4);
                int h2 = (ni & 1) * 2;
                mmah(acc[mi][ni], Af, Bf[h2], Bf[h2 + 1]);
            }
        }
    }
}

__device__ __forceinline__ void gemm_tn(float acc[2][4][4], uint32_t smbase,
    const __half* A, int lda,
    const __half* B, int ldb,
    int kt, int m0, int n0, int tid, int lane, int wm, int wn)
{
    __syncthreads();
    ld_stage(smbase, A, lda, B, ldb, m0, n0, 0, tid);
    cpcommit();
    if (kt > 1) ld_stage(smbase + 2 * STAGE_H, A, lda, B, ldb, m0, n0, BKT, tid);
    cpcommit();

    for (int t = 0; t < kt; t++) {
        cpwait<1>();
        __syncthreads();
        compute_stage(acc, smbase + (t % 3) * 2 * STAGE_H, lane, wm, wn);
        if (t + 2 < kt)
            ld_stage(smbase + ((t + 2) % 3) * 2 * STAGE_H,
                     A, lda, B, ldb, m0, n0, (t + 2) * BKT, tid);
        cpcommit();
    }
    cpwait<0>();
}

// ---------------------------------------------------------------------------
// fp32 SIMT kpre (runs once)
// ---------------------------------------------------------------------------
#define PBM 128
__device__ __forceinline__ void mm_compute(float acc[8][4],
    const float As[BK][PBM + 4], const float Bs[BK][BN], int tx, int ty)
{
#pragma unroll
    for (int kk = 0; kk < BK; kk++) {
        float4 a0 = *reinterpret_cast<const float4*>(&As[kk][ty * 8]);
        float4 a1 = *reinterpret_cast<const float4*>(&As[kk][ty * 8 + 4]);
        float4 b  = *reinterpret_cast<const float4*>(&Bs[kk][tx * 4]);
        float av[8] = {a0.x, a0.y, a0.z, a0.w, a1.x, a1.y, a1.z, a1.w};
        float bv[4] = {b.x, b.y, b.z, b.w};
#pragma unroll
        for (int i = 0; i < 8; i++)
#pragma unroll
            for (int j = 0; j < 4; j++)
                acc[i][j] = fmaf(av[i], bv[j], acc[i][j]);
    }
}
__device__ __forceinline__ void st_nt(float As[BK][PBM + 4], float Bs[BK][BN],
                                      int r, int c, float4 va0, float4 va1, float4 vb)
{
    As[c + 0][r] = va0.x; As[c + 1][r] = va0.y; As[c + 2][r] = va0.z; As[c + 3][r] = va0.w;
    As[c + 0][r + 64] = va1.x; As[c + 1][r + 64] = va1.y; As[c + 2][r + 64] = va1.z; As[c + 3][r + 64] = va1.w;
    Bs[c + 0][r] = vb.x; Bs[c + 1][r] = vb.y; Bs[c + 2][r] = vb.z; Bs[c + 3][r] = vb.w;
}

__global__ void __launch_bounds__(NTHR) kpre(
    const float* __restrict__ x, const float* __restrict__ u,
    const float* __restrict__ W_in, const float* __restrict__ b_in,
    const float* __restrict__ Wxs, const float* __restrict__ bs)
{
    __shared__ float As[2][BK][PBM + 4];
    __shared__ float Bs[2][BK][BN];
    const int tid = threadIdx.x, tx = tid & 15, ty = tid >> 4;
    const int m0 = blockIdx.y * PBM, n0 = blockIdx.x * BN;
    const int s = blockIdx.z;
    const float* W    = (s == 0) ? W_in : Wxs + (size_t)(s - 1) * HH;
    const float* bias = (s == 0) ? b_in : bs + (size_t)(s - 1) * Hd;
    float* Out = g_buf + O_C + (size_t)s * BH;

    float acc[8][4];
#pragma unroll
    for (int i = 0; i < 8; i++)
#pragma unroll
        for (int j = 0; j < 4; j++) acc[i][j] = 0.f;

    const int r = tid >> 2;
    const int c = (tid & 3) * 4;
    const int kt = 576 / BK;
    const float* Bp = W + (size_t)(n0 + r) * Hd + 256 + c;

    float4 va0, va1, vb;
    va0 = *reinterpret_cast<const float4*>(&x[(size_t)(m0 + r) * 512 + c]);
    va1 = *reinterpret_cast<const float4*>(&x[(size_t)(m0 + r + 64) * 512 + c]);
    vb  = *reinterpret_cast<const float4*>(Bp);
    __syncthreads();
    st_nt(As[0], Bs[0], r, c, va0, va1, vb);
    __syncthreads();

    for (int t = 0; t < kt; t++) {
        int buf = t & 1;
        if (t + 1 < kt) {
            int k = (t + 1) * BK + c;
            if (k < 512) {
                va0 = *reinterpret_cast<const float4*>(&x[(size_t)(m0 + r) * 512 + k]);
                va1 = *reinterpret_cast<const float4*>(&x[(size_t)(m0 + r + 64) * 512 + k]);
            } else {
                va0 = *reinterpret_cast<const float4*>(&u[(size_t)(m0 + r) * 64 + (k - 512)]);
                va1 = *reinterpret_cast<const float4*>(&u[(size_t)(m0 + r + 64) * 64 + (k - 512)]);
            }
            vb = *reinterpret_cast<const float4*>(Bp + (t + 1) * BK);
        }
        mm_compute(acc, As[buf], Bs[buf], tx, ty);
        if (t + 1 < kt) st_nt(As[buf ^ 1], Bs[buf ^ 1], r, c, va0, va1, vb);
        __syncthreads();
    }

    const float4 b4 = *reinterpret_cast<const float4*>(&bias[n0 + tx * 4]);
#pragma unroll
    for (int i = 0; i < 8; i++) {
        int m = m0 + ty * 8 + i;
        float4 o;
        o.x = acc[i][0] + b4.x; o.y = acc[i][1] + b4.y;
        o.z = acc[i][2] + b4.z; o.w = acc[i][3] + b4.w;
        *reinterpret_cast<float4*>(&Out[(size_t)m * Hd + n0 + tx * 4]) = o;
    }
}

// ---------------------------------------------------------------------------
// Prep
// ---------------------------------------------------------------------------
__global__ void kprep(const float* __restrict__ Wzs, const float* __restrict__ wz_out,
                      const float* __restrict__ W_in, const float* __restrict__ Wxs,
                      float* __restrict__ Z)
{
    __half* hf = g_hf;
    float* SWZO = g_buf + O_SWZO;
    float* Mm = g_buf + O_M;
    float* Vv = g_buf + O_V;
    const int n = 3 * HH;
    for (int i = blockIdx.x * blockDim.x + threadIdx.x; i < n;
         i += gridDim.x * blockDim.x) {
        int l = i / HH, o = i - l * HH;
        int r = o / Hd, c = o - r * Hd;
        float w = sp_(Wzs[i]);
        hf[OB_BC + (size_t)l * (832ull * HW) + (size_t)r * HW + c] = __float2half_rn(w * SCL);
        hf[OB_SWZT + (size_t)l * HH + (size_t)c * Hd + r] = __float2half_rn(w);
        if (c < Zd) {
            float wx = Wxs[i] * SCL;
            hf[OB_BC + (size_t)l * (832ull * HW) + (size_t)r * HW + Hd + c] = __float2half_rn(wx);
            hf[OB_WXZT + (size_t)l * (Zd * Hd) + (size_t)c * Hd + r] = __float2half_rn(wx);
            if (l == 0) {
                float wi = W_in[o] * SCL;
                hf[OB_WINZ + (size_t)r * Zd + c] = __float2half_rn(wi);
                hf[OB_WINZT + (size_t)c * Hd + r] = __float2half_rn(wi);
            }
        }
        if (i < Hd) SWZO[i] = sp_(wz_out[i]);
        if (i < BZ) {
            Z[i] = 0.f; Mm[i] = 0.f; Vv[i] = 0.f;
            hf[OB_Z + i] = __float2half_rn(0.f);
            int m = i / Zd, j = i - m * Zd;
            size_t tb = (size_t)m * HW + Hd + j;
            hf[OB_H + tb] = __float2half_rn(0.f);
            hf[OB_H + BHW + tb] = __float2half_rn(0.f);
            hf[OB_H + 2ull * BHW + tb] = __float2half_rn(0.f);
        }
    }
}

// ---------------------------------------------------------------------------
// Forward: MODE 0 input (A=Zq K=256), MODE 1/2 hidden (A=[h|z] K=1088, B=BCAT)
// ---------------------------------------------------------------------------
template<int MODE>
__global__ void __launch_bounds__(GT, 4) kfwd(
    const __half* __restrict__ A1, const __half* __restrict__ B1,
    const float* __restrict__ C0, __half* __restrict__ O)
{
    extern __shared__ __align__(16) char dsm[];
    uint32_t smbase = (uint32_t)__cvta_generic_to_shared(dsm);
    const int tid = threadIdx.x, lane = tid & 31, wid = tid >> 5;
    const int wm = (wid >> 1) * 32, wn = (wid & 1) * 32;
    const int m0 = blockIdx.y * BM, n0 = blockIdx.x * BN;

    float acc[2][4][4];
#pragma unroll
    for (int a = 0; a < 2; a++)
#pragma unroll
        for (int b = 0; b < 4; b++)
#pragma unroll
            for (int d = 0; d < 4; d++) acc[a][b][d] = 0.f;

    const int lda = (MODE == 0) ? Zd : HW;
    const int kt  = (MODE == 0) ? (Zd / BKT) : (HW / BKT);
    gemm_tn(acc, smbase, A1, lda, B1, lda, kt, m0, n0, tid, lane, wm, wn);

    const int ostr = (MODE == 2) ? Hd : HW;
    const int l4 = lane >> 2, l2 = (lane & 3) * 2;
#pragma unroll
    for (int mi = 0; mi < 2; mi++)
#pragma unroll
    for (int ni = 0; ni < 4; ni++) {
        int mA = m0 + wm + mi * 16 + l4;
        int n  = n0 + wn + ni * 8 + l2;
        size_t iCA = (size_t)mA * Hd + n, iCB = iCA + 8ull * Hd;
        size_t iOA = (size_t)mA * ostr + n, iOB = iOA + 8ull * ostr;
        float2 cA = *(const float2*)(C0 + iCA);
        float2 cB = *(const float2*)(C0 + iCB);
        float v0 = acc[mi][ni][0] + cA.x, v1 = acc[mi][ni][1] + cA.y;
        float v2 = acc[mi][ni][2] + cB.x, v3 = acc[mi][ni][3] + cB.y;
        if (MODE == 2) {
            const float* SWZO = g_buf + O_SWZO;
            float2 s2 = *(const float2*)(SWZO + n);
            v0 = s2.x * sig_(v0); v1 = s2.y * sig_(v1);
            v2 = s2.x * sig_(v2); v3 = s2.y * sig_(v3);
            *(__half2*)(O + iOA) = __floats2half2_rn(v0, v1);
            *(__half2*)(O + iOB) = __floats2half2_rn(v2, v3);
        } else {
            v0 = sp_(v0); v1 = sp_(v1); v2 = sp_(v2); v3 = sp_(v3);
            *(__half2*)(O + iOA) = __floats2half2_rn(v0 * ISCL, v1 * ISCL);
            *(__half2*)(O + iOB) = __floats2half2_rn(v2 * ISCL, v3 * ISCL);
        }
    }
}

// ---------------------------------------------------------------------------
// Backward hidden layer (combined d-path / g-path, 17-col grid).
// ---------------------------------------------------------------------------
template<bool FIRSTG>
__global__ void __launch_bounds__(GT, 4) kbwd(
    const __half* __restrict__ D,
    const __half* __restrict__ ST, const __half* __restrict__ XT,
    const __half* __restrict__ Hp, __half* __restrict__ O,
    const float* __restrict__ wx_out, float rs, float gs)
{
    extern __shared__ __align__(16) char dsm[];
    uint32_t smbase = (uint32_t)__cvta_generic_to_shared(dsm);
    const int tid = threadIdx.x, lane = tid & 31, wid = tid >> 5;
    const int wm = (wid >> 1) * 32, wn = (wid & 1) * 32;
    const int m0 = blockIdx.y * BM, n0 = blockIdx.x * BN;
    const bool gpath = (n0 >= Hd);
    const int nb = gpath ? (n0 - Hd) : n0;

    float acc[2][4][4];
#pragma unroll
    for (int a = 0; a < 2; a++)
#pragma unroll
        for (int b = 0; b < 4; b++)
#pragma unroll
            for (int d = 0; d < 4; d++) acc[a][b][d] = 0.f;

    gemm_tn(acc, smbase, D, Hd, gpath ? XT : ST, Hd, Hd / BKT,
            m0, nb, tid, lane, wm, wn);

    const int l4 = lane >> 2, l2 = (lane & 3) * 2;
    if (!gpath) {
#pragma unroll
        for (int mi = 0; mi < 2; mi++)
#pragma unroll
        for (int ni = 0; ni < 4; ni++) {
            int mA = m0 + wm + mi * 16 + l4;
            int n  = n0 + wn + ni * 8 + l2;
            size_t iA = (size_t)mA * Hd + n, iB = iA + 8ull * Hd;
            size_t hA = (size_t)mA * HW + n, hB = hA + 8ull * HW;
            __half2 h2A = *(const __half2*)(Hp + hA);
            __half2 h2B = *(const __half2*)(Hp + hB);
            float d0 = acc[mi][ni][0] * sig_from_h(__half2float(h2A.x) * SCL) * rs;
            float d1 = acc[mi][ni][1] * sig_from_h(__half2float(h2A.y) * SCL) * rs;
            float d2 = acc[mi][ni][2] * sig_from_h(__half2float(h2B.x) * SCL) * rs;
            float d3 = acc[mi][ni][3] * sig_from_h(__half2float(h2B.y) * SCL) * rs;
            *(__half2*)(O + iA) = __floats2half2_rn(d0, d1);
            *(__half2*)(O + iB) = __floats2half2_rn(d2, d3);
        }
    } else {
        float* G = g_buf + O_G;
#pragma unroll
        for (int mi = 0; mi < 2; mi++)
#pragma unroll
        for (int ni = 0; ni < 4; ni++) {
            int mA = m0 + wm + mi * 16 + l4;
            int np = nb + wn + ni * 8 + l2;
            size_t gA = (size_t)mA * Zd + np, gB = gA + 8ull * Zd;
            float2 bA, bB;
            if (FIRSTG) {
                float2 w2 = *(const float2*)(wx_out + np);
                bA = w2; bB = w2;
            } else {
                bA = *(const float2*)(G + gA);
                bB = *(const float2*)(G + gB);
            }
            float2 oA, oB;
            oA.x = bA.x + acc[mi][ni][0] * gs; oA.y = bA.y + acc[mi][ni][1] * gs;
            oB.x = bB.x + acc[mi][ni][2] * gs; oB.y = bB.y + acc[mi][ni][3] * gs;
            *(float2*)(G + gA) = oA;
            *(float2*)(G + gB) = oB;
        }
    }
}

// ---------------------------------------------------------------------------
// Final backward + Adam
// ---------------------------------------------------------------------------
__global__ void __launch_bounds__(GT, 4) kbwdin(
    const __half* __restrict__ D, const __half* __restrict__ WT,
    float* __restrict__ Z, __half* __restrict__ Zq, __half* __restrict__ Hb,
    float bc1, float bc2, float gs)
{
    extern __shared__ __align__(16) char dsm[];
    uint32_t smbase = (uint32_t)__cvta_generic_to_shared(dsm);
    const int tid = threadIdx.x, lane = tid & 31, wid = tid >> 5;
    const int wm = (wid >> 1) * 32, wn = (wid & 1) * 32;
    const int m0 = blockIdx.y * BM, n0 = blockIdx.x * BN;

    float acc[2][4][4];
#pragma unroll
    for (int a = 0; a < 2; a++)
#pragma unroll
        for (int b = 0; b < 4; b++)
#pragma unroll
            for (int d = 0; d < 4; d++) acc[a][b][d] = 0.f;

    gemm_tn(acc, smbase, D, Hd, WT, Hd, Hd / BKT, m0, n0, tid, lane, wm, wn);

    const float* G = g_buf + O_G;
    float* Mm = g_buf + O_M;
    float* Vv = g_buf + O_V;
    const int l4 = lane >> 2, l2 = (lane & 3) * 2;
#pragma unroll
    for (int mi = 0; mi < 2; mi++)
#pragma unroll
    for (int ni = 0; ni < 4; ni++) {
        int mA = m0 + wm + mi * 16 + l4;
        int np = n0 + wn + ni * 8 + l2;
#pragma unroll
        for (int hh = 0; hh < 2; hh++) {
            int mrow = mA + hh * 8;
            size_t id = (size_t)mrow * Zd + np;
            float g0 = G[id]     + acc[mi][ni][hh * 2 + 0] * gs;
            float g1 = G[id + 1] + acc[mi][ni][hh * 2 + 1] * gs;
            float2 m2 = *(const float2*)(Mm + id);
            float2 v2 = *(const float2*)(Vv + id);
            float nm0 = 0.9f * m2.x + 0.1f * g0;
            float nm1 = 0.9f * m2.y + 0.1f * g1;
            float nv0 = 0.999f * v2.x + 0.001f * g0 * g0;
            float nv1 = 0.999f * v2.y + 0.001f * g1 * g1;
            *(float2*)(Mm + id) = make_float2(nm0, nm1);
            *(float2*)(Vv + id) = make_float2(nv0, nv1);
            float2 z2 = *(const float2*)(Z + id);
            z2.x -= 0.01f * (nm0 * bc1) / (sqrtf(nv0 * bc2) + 1e-8f);
            z2.y -= 0.01f * (nm1 * bc1) / (sqrtf(nv1 * bc2) + 1e-8f);
            *(float2*)(Z + id) = z2;
            __half2 zq = __floats2half2_rn(z2.x * ISCL, z2.y * ISCL);
            *(__half2*)(Zq + id) = zq;
            size_t tb = (size_t)mrow * HW + Hd + np;
            *(__half2*)(Hb + tb) = zq;
            *(__half2*)(Hb + BHW + tb) = zq;
            *(__half2*)(Hb + 2ull * BHW + tb) = zq;
        }
    }
}

// ---------------------------------------------------------------------------
// Host driver (single stream)
// ---------------------------------------------------------------------------
extern "C" void kernel_launch(void* const* d_in, const int* in_sizes, int n_in,
                              void* d_out, int out_size)
{
    (void)in_sizes; (void)n_in; (void)out_size;
    const float* x      = (const float*)d_in[0];
    const float* u      = (const float*)d_in[1];
    const float* W_in   = (const float*)d_in[2];
    const float* b_in   = (const float*)d_in[3];
    const float* Wzs    = (const float*)d_in[4];
    const float* Wxs    = (const float*)d_in[5];
    const float* bs     = (const float*)d_in[6];
    const float* wz_out = (const float*)d_in[7];
    const float* wx_out = (const float*)d_in[8];
    float* z = (float*)d_out;

    float* buf = nullptr;
    { void* p = nullptr; cudaGetSymbolAddress(&p, g_buf); buf = (float*)p; }
    __half* hb = nullptr;
    { void* p = nullptr; cudaGetSymbolAddress(&p, g_hf); hb = (__half*)p; }

    float* C = buf + O_C;

    static bool attr_done = false;
    if (!attr_done) {
        cudaFuncSetAttribute(kfwd<0>, cudaFuncAttributeMaxDynamicSharedMemorySize, SMEM_BYTES);
        cudaFuncSetAttribute(kfwd<1>, cudaFuncAttributeMaxDynamicSharedMemorySize, SMEM_BYTES);
        cudaFuncSetAttribute(kfwd<2>, cudaFuncAttributeMaxDynamicSharedMemorySize, SMEM_BYTES);
        cudaFuncSetAttribute(kbwd<true>,  cudaFuncAttributeMaxDynamicSharedMemorySize, SMEM_BYTES);
        cudaFuncSetAttribute(kbwd<false>, cudaFuncAttributeMaxDynamicSharedMemorySize, SMEM_BYTES);
        cudaFuncSetAttribute(kbwdin, cudaFuncAttributeMaxDynamicSharedMemorySize, SMEM_BYTES);
        attr_done = true;
    }

    kprep<<<2048, 512>>>(Wzs, wz_out, W_in, Wxs, z);
    kpre<<<dim3(Hd / BN, Bsz / PBM, 4), NTHR>>>(x, u, W_in, b_in, Wxs, bs);

    const dim3 gF(Hd / BN, Bsz / BM);            // 13 x 64
    const dim3 gB((Hd + Zd) / BN, Bsz / BM);     // 17 x 64
    const dim3 gI(Zd / BN, Bsz / BM);            // 4 x 64
    const dim3 blk(GT);

    __half *Zq = hb + OB_Z;
    __half *DA = hb + OB_DA, *DB = hb + OB_DB;
    __half *Hb = hb + OB_H;

    const float RS_32 = 1.0f;
    const float RS_21 = 0.0625f;            // 2^-4
    const float RS_10 = 0.001953125f;       // 2^-9
    const float GS_3  = 0.03125f;           // 2^-5
    const float GS_2  = 0.03125f;           // 2^-5
    const float GS_1  = 0.5f;               // 2^-1
    const float GS_0  = 256.0f;             // 2^8

    for (int t = 0; t < NSTEPS; t++) {
        kfwd<0><<<gF, blk, SMEM_BYTES>>>(Zq, hb + OB_WINZ, C, Hb);
        kfwd<1><<<gF, blk, SMEM_BYTES>>>(
            Hb, hb + OB_BC, C + 1ull * BH, Hb + BHW);
        kfwd<1><<<gF, blk, SMEM_BYTES>>>(
            Hb + BHW, hb + OB_BC + 832ull * HW, C + 2ull * BH, Hb + 2ull * BHW);
        kfwd<2><<<gF, blk, SMEM_BYTES>>>(
            Hb + 2ull * BHW, hb + OB_BC + 2ull * 832ull * HW, C + 3ull * BH, DA);
        kbwd<true><<<gB, blk, SMEM_BYTES>>>(
            DA, hb + OB_SWZT + 2ull * HH, hb + OB_WXZT + 2ull * (Zd * Hd),
            Hb + 2ull * BHW, DB, wx_out, RS_32, GS_3);
        kbwd<false><<<gB, blk, SMEM_BYTES>>>(
            DB, hb + OB_SWZT + 1ull * HH, hb + OB_WXZT + 1ull * (Zd * Hd),
            Hb + BHW, DA, wx_out, RS_21, GS_2);
        kbwd<false><<<gB, blk, SMEM_BYTES>>>(
            DA, hb + OB_SWZT, hb + OB_WXZT,
            Hb, DB, wx_out, RS_10, GS_1);
        double p1 = 1.0, p2 = 1.0;
        for (int q = 0; q <= t; q++) { p1 *= 0.9; p2 *= 0.999; }
        float bc1 = (float)(1.0 / (1.0 - p1));
        float bc2 = (float)(1.0 / (1.0 - p2));
        kbwdin<<<gI, blk, SMEM_BYTES>>>(
            DB, hb + OB_WINZT, z, Zq, Hb, bc1, bc2, GS_0);
    }
}